// round 2
// baseline (speedup 1.0000x reference)
#include <cuda_runtime.h>
#include <cuda_fp16.h>

#define NN 768
#define CC 384
#define CZd 128
#define HHd 16
#define CHD 24
#define NP (NN*NN)
#define INFV 1e9f
#define EPSV 1e-5f

typedef unsigned long long u64;
typedef unsigned int u32;

// ------------------------- device scratch (no runtime alloc) ----------------
__device__ float g_an[NN*CC];
__device__ float g_q[NN*CC];
__device__ float g_k[NN*CC];
__device__ float g_v[NN*CC];
__device__ float g_g[NN*CC];
__device__ float g_o[NN*CC];
__device__ float g_Wpp[2048];          // packed [c2][h][2] : {Wp[2c][h], Wp[2c+1][h]}
__device__ float g_S[HHd];
__device__ float g_Cb[HHd];
__device__ __half g_bias[(size_t)HHd*NP];   // [h][i*768 + j]

// ------------------------- packed f32x2 helpers (sm_103a) -------------------
__device__ __forceinline__ u64 pk2(float x, float y){
    u64 r; asm("mov.b64 %0,{%1,%2};" : "=l"(r) : "r"(__float_as_uint(x)), "r"(__float_as_uint(y))); return r;
}
__device__ __forceinline__ float2 up2(u64 v){
    u32 a,b; asm("mov.b64 {%0,%1},%2;" : "=r"(a), "=r"(b) : "l"(v));
    return make_float2(__uint_as_float(a), __uint_as_float(b));
}
__device__ __forceinline__ u64 ffma2(u64 a, u64 b, u64 c){
    u64 d; asm("fma.rn.f32x2 %0,%1,%2,%3;" : "=l"(d) : "l"(a), "l"(b), "l"(c)); return d;
}
__device__ __forceinline__ u64 fmul2(u64 a, u64 b){
    u64 d; asm("mul.rn.f32x2 %0,%1,%2;" : "=l"(d) : "l"(a), "l"(b)); return d;
}
__device__ __forceinline__ u64 fadd2(u64 a, u64 b){
    u64 d; asm("add.rn.f32x2 %0,%1,%2;" : "=l"(d) : "l"(a), "l"(b)); return d;
}
__device__ __forceinline__ float sigmoidf_(float x){ return 1.f/(1.f + __expf(-x)); }

// ------------------------- kernel 1: fold LN(z) weights ---------------------
__global__ void k_prep(const float* __restrict__ lnzw, const float* __restrict__ lnzb,
                       const float* __restrict__ Wz){
    __shared__ float sw[128][17];
    __shared__ float sb[128][17];
    int c = threadIdx.x;   // 0..127
    float w = lnzw[c], b = lnzb[c];
    #pragma unroll
    for(int h=0; h<16; h++){
        float wz = Wz[c*16 + h];
        float wp = w*wz;
        sw[c][h] = wp;
        sb[c][h] = b*wz;
        g_Wpp[(c>>1)*32 + h*2 + (c&1)] = wp;
    }
    __syncthreads();
    if(c < 16){
        float s = 0.f, cb = 0.f;
        for(int j=0; j<128; j++){ s += sw[j][c]; cb += sb[j][c]; }
        g_S[c] = s; g_Cb[c] = cb;
    }
}

// ------------------------- kernel 2: LayerNorm(a) ---------------------------
__global__ void k_lna(const float* __restrict__ a, const float* __restrict__ w,
                      const float* __restrict__ b){
    int warp = threadIdx.x >> 5, lane = threadIdx.x & 31;
    int row = blockIdx.x*8 + warp;
    const float* ar = a + (size_t)row*CC;
    float v[12]; float s = 0.f, ss = 0.f;
    #pragma unroll
    for(int r=0; r<12; r++){ v[r] = ar[lane + r*32]; s += v[r]; ss += v[r]*v[r]; }
    #pragma unroll
    for(int o=16; o; o>>=1){ s += __shfl_xor_sync(~0u, s, o); ss += __shfl_xor_sync(~0u, ss, o); }
    float mu = s * (1.f/CC);
    float rs = rsqrtf(ss*(1.f/CC) - mu*mu + EPSV);
    float* dr = g_an + (size_t)row*CC;
    #pragma unroll
    for(int r=0; r<12; r++){
        int cc = lane + r*32;
        dr[cc] = (v[r]-mu)*rs*w[cc] + b[cc];
    }
}

// ------------------------- kernel 3: pair bias (fused LN(z)@Wz) -------------
// grid (6, 768): blockIdx.y = i, blockIdx.x = j-tile of 128. 128 threads.
__global__ void __launch_bounds__(128) k_bias(const float* __restrict__ z){
    __shared__ __align__(16) float zs[128*68];    // 128 j rows x 64 c (per phase), pad 68
    __shared__ __align__(16) float swp[2048];     // packed Wp
    __shared__ float smu[128], srs[128];
    __shared__ float sS[16], sCb[16];
    int t = threadIdx.x;
    int i  = blockIdx.y;
    int j0 = blockIdx.x*128;
    #pragma unroll
    for(int r=0; r<16; r++) swp[r*128 + t] = g_Wpp[r*128 + t];

    const float* zbase = z + ((size_t)i*NN + j0)*CZd;
    float sum = 0.f, ssq = 0.f;
    u64 acc[16];
    #pragma unroll
    for(int q=0; q<16; q++) acc[q] = 0ull;
    int hg = t & 3, jg = t >> 2;

    #pragma unroll
    for(int p=0; p<2; p++){
        __syncthreads();
        // cooperative coalesced load of 128 j x 64 c (half of CZ)
        #pragma unroll
        for(int r=0; r<16; r++){
            int idx = t + 128*r;
            int j = idx >> 4, c4 = idx & 15;
            float4 zv = *(const float4*)(zbase + (size_t)j*CZd + p*64 + c4*4);
            *(float4*)&zs[j*68 + c4*4] = zv;
        }
        __syncthreads();
        // stats for j = t
        #pragma unroll
        for(int c2=0; c2<32; c2++){
            float2 zz = up2(*(const u64*)&zs[t*68 + 2*c2]);
            sum += zz.x + zz.y;
            ssq = fmaf(zz.x, zz.x, ssq); ssq = fmaf(zz.y, zz.y, ssq);
        }
        // dots: 4 j (stride 32) x 4 h per thread
        const float* wbase = swp + p*32*32 + hg*8;
        #pragma unroll 4
        for(int c2=0; c2<32; c2++){
            const u64* wr = (const u64*)(wbase + c2*32);
            u64 w0 = wr[0], w1 = wr[1], w2 = wr[2], w3 = wr[3];
            #pragma unroll
            for(int s4=0; s4<4; s4++){
                u64 zv = *(const u64*)&zs[(jg + 32*s4)*68 + 2*c2];
                acc[s4*4+0] = ffma2(zv, w0, acc[s4*4+0]);
                acc[s4*4+1] = ffma2(zv, w1, acc[s4*4+1]);
                acc[s4*4+2] = ffma2(zv, w2, acc[s4*4+2]);
                acc[s4*4+3] = ffma2(zv, w3, acc[s4*4+3]);
            }
        }
    }
    float mu = sum * (1.f/128.f);
    float rs = rsqrtf(ssq*(1.f/128.f) - mu*mu + EPSV);
    smu[t] = mu; srs[t] = rs;
    if(t < 16){ sS[t] = g_S[t]; sCb[t] = g_Cb[t]; }
    __syncthreads();

    // finalize into half staging (reuse zs memory)
    __half* sh = (__half*)zs;
    #pragma unroll
    for(int s4=0; s4<4; s4++){
        int j = jg + 32*s4;
        float m_ = smu[j], r_ = srs[j];
        #pragma unroll
        for(int hi=0; hi<4; hi++){
            int h = hg*4 + hi;
            float2 d = up2(acc[s4*4+hi]);
            float bv = r_*((d.x + d.y) - m_*sS[h]) + sCb[h];
            sh[h*128 + j] = __float2half(bv);
        }
    }
    __syncthreads();
    const u32* sh2 = (const u32*)sh;
    #pragma unroll
    for(int r=0; r<8; r++){
        int lin = r*128 + t;
        int h = lin >> 6, j2 = lin & 63;
        *(u32*)&g_bias[(size_t)h*NP + (size_t)i*NN + j0 + j2*2] = sh2[h*64 + j2];
    }
}

// ------------------------- kernel 4: QKVG projections -----------------------
// grid (6, 12, 4), 128 threads. C[m][n] = an @ W, +bg for z==3.
__global__ void __launch_bounds__(128) k_proj(const float* __restrict__ Wq,
                                              const float* __restrict__ Wk2,
                                              const float* __restrict__ Wv2,
                                              const float* __restrict__ Wg2,
                                              const float* __restrict__ bg){
    __shared__ __align__(16) float As[64*36];
    __shared__ __align__(16) float Bs[32*68];
    int t = threadIdx.x;
    int n0 = blockIdx.x*64, m0 = blockIdx.y*64, zz = blockIdx.z;
    const float* W = (zz==0) ? Wq : (zz==1) ? Wk2 : (zz==2) ? Wv2 : Wg2;
    float* Cd = (zz==0) ? g_q : (zz==1) ? g_k : (zz==2) ? g_v : g_g;
    u64 acc[4][4];
    #pragma unroll
    for(int r=0;r<4;r++){ acc[r][0]=0; acc[r][1]=0; acc[r][2]=0; acc[r][3]=0; }
    int tm = t & 15, tn = t >> 4;

    for(int k0=0; k0<CC; k0+=32){
        __syncthreads();
        #pragma unroll
        for(int r=0; r<4; r++){
            int idx = t + 128*r;
            int row = idx >> 3, c4 = idx & 7;
            float4 av = *(const float4*)&g_an[(size_t)(m0+row)*CC + k0 + c4*4];
            *(float4*)&As[row*36 + c4*4] = av;
            int kr = idx >> 4, n4 = idx & 15;
            float4 bv = *(const float4*)&W[(size_t)(k0+kr)*CC + n0 + n4*4];
            *(float4*)&Bs[kr*68 + n4*4] = bv;
        }
        __syncthreads();
        #pragma unroll 8
        for(int kk=0; kk<32; kk++){
            u64 b0 = *(const u64*)&Bs[kk*68 + tn*8 + 0];
            u64 b1 = *(const u64*)&Bs[kk*68 + tn*8 + 2];
            u64 b2 = *(const u64*)&Bs[kk*68 + tn*8 + 4];
            u64 b3 = *(const u64*)&Bs[kk*68 + tn*8 + 6];
            #pragma unroll
            for(int r=0; r<4; r++){
                float a = As[(tm + 16*r)*36 + kk];
                u64 a2 = pk2(a, a);
                acc[r][0] = ffma2(a2, b0, acc[r][0]);
                acc[r][1] = ffma2(a2, b1, acc[r][1]);
                acc[r][2] = ffma2(a2, b2, acc[r][2]);
                acc[r][3] = ffma2(a2, b3, acc[r][3]);
            }
        }
    }
    #pragma unroll
    for(int r=0; r<4; r++){
        int m = m0 + tm + 16*r;
        #pragma unroll
        for(int p=0; p<4; p++){
            int n = n0 + tn*8 + 2*p;
            float2 vv = up2(acc[r][p]);
            if(zz == 3){ vv.x += bg[n]; vv.y += bg[n+1]; }
            *(float2*)&Cd[(size_t)m*CC + n] = vv;
        }
    }
}

// ------------------------- kernel 5: attention -------------------------------
// grid (24, 16): blockIdx.x = q-tile of 32, blockIdx.y = h. 256 threads.
__global__ void __launch_bounds__(256) k_attn(const float* __restrict__ mask){
    __shared__ __align__(16) float qs[32*26];
    __shared__ __align__(16) float ks[64*26];
    __shared__ __align__(16) float vs[64*26];
    __shared__ float smb[NN];
    int t = threadIdx.x;
    int h = blockIdx.y, q0 = blockIdx.x*32;
    const float scale = 0.20412414523193154f;  // 24^-0.5

    for(int idx=t; idx<32*24; idx+=256){
        int qq = idx/24, c = idx - qq*24;
        qs[qq*26 + c] = g_q[(size_t)(q0+qq)*CC + h*CHD + c] * scale;
    }
    for(int idx=t; idx<NN; idx+=256) smb[idx] = INFV*(mask[idx] - 1.f);
    __syncthreads();

    int qq = t >> 3, k8 = t & 7;
    u64 qv[12];
    #pragma unroll
    for(int i2=0; i2<12; i2++) qv[i2] = *(const u64*)&qs[qq*26 + 2*i2];

    float mx = -1e30f, l = 0.f;
    u64 acc[12];
    #pragma unroll
    for(int i2=0; i2<12; i2++) acc[i2] = 0ull;
    const __half* bptr = g_bias + (size_t)h*NP + (size_t)(q0+qq)*NN;

    for(int kt=0; kt<NN; kt+=64){
        __syncthreads();
        for(int idx=t; idx<64*24; idx+=256){
            int kk = idx/24, c = idx - kk*24;
            ks[kk*26 + c] = g_k[(size_t)(kt+kk)*CC + h*CHD + c];
            vs[kk*26 + c] = g_v[(size_t)(kt+kk)*CC + h*CHD + c];
        }
        __syncthreads();
        #pragma unroll 2
        for(int ii=0; ii<8; ii++){
            int kk = k8 + ii*8;
            u64 d2 = 0ull;
            #pragma unroll
            for(int i2=0; i2<12; i2++) d2 = ffma2(qv[i2], *(const u64*)&ks[kk*26 + 2*i2], d2);
            float2 dd = up2(d2);
            float s = dd.x + dd.y + __half2float(bptr[kt+kk]) + smb[kt+kk];
            if(s > mx){
                float f = __expf(mx - s);
                l *= f;
                u64 f2 = pk2(f, f);
                #pragma unroll
                for(int i2=0; i2<12; i2++) acc[i2] = fmul2(acc[i2], f2);
                mx = s;
            }
            float e = __expf(s - mx);
            l += e;
            u64 e2 = pk2(e, e);
            #pragma unroll
            for(int i2=0; i2<12; i2++) acc[i2] = ffma2(*(const u64*)&vs[kk*26 + 2*i2], e2, acc[i2]);
        }
    }
    // merge the 8 lanes that share a q
    #pragma unroll
    for(int off=1; off<8; off<<=1){
        float om = __shfl_xor_sync(~0u, mx, off);
        float ol = __shfl_xor_sync(~0u, l,  off);
        float nm = fmaxf(mx, om);
        float fs = __expf(mx - nm), fo = __expf(om - nm);
        l = l*fs + ol*fo;
        u64 fs2 = pk2(fs, fs), fo2 = pk2(fo, fo);
        #pragma unroll
        for(int i2=0; i2<12; i2++){
            float2 av = up2(acc[i2]);
            float ox = __shfl_xor_sync(~0u, av.x, off);
            float oy = __shfl_xor_sync(~0u, av.y, off);
            acc[i2] = fadd2(fmul2(acc[i2], fs2), fmul2(pk2(ox, oy), fo2));
        }
        mx = nm;
    }
    if(k8 == 0){
        float inv = 1.f / l;
        u64 iv = pk2(inv, inv);
        float* op = g_o + (size_t)(q0+qq)*CC + h*CHD;
        #pragma unroll
        for(int i2=0; i2<12; i2++){
            float2 vv = up2(fmul2(acc[i2], iv));
            *(float2*)&op[2*i2] = vv;
        }
    }
}

// ------------------------- kernel 6: gated output projection ----------------
// grid (6, 12), 128 threads. out = (sigmoid(g) * o) @ Wo + bo.
__global__ void __launch_bounds__(128) k_oproj(const float* __restrict__ Wo,
                                               const float* __restrict__ bo,
                                               float* __restrict__ out){
    __shared__ __align__(16) float As[64*36];
    __shared__ __align__(16) float Bs[32*68];
    int t = threadIdx.x;
    int n0 = blockIdx.x*64, m0 = blockIdx.y*64;
    u64 acc[4][4];
    #pragma unroll
    for(int r=0;r<4;r++){ acc[r][0]=0; acc[r][1]=0; acc[r][2]=0; acc[r][3]=0; }
    int tm = t & 15, tn = t >> 4;

    for(int k0=0; k0<CC; k0+=32){
        __syncthreads();
        #pragma unroll
        for(int r=0; r<4; r++){
            int idx = t + 128*r;
            int row = idx >> 3, c4 = idx & 7;
            size_t aoff = (size_t)(m0+row)*CC + k0 + c4*4;
            float4 ov = *(const float4*)&g_o[aoff];
            float4 gv = *(const float4*)&g_g[aoff];
            float4 av;
            av.x = ov.x * sigmoidf_(gv.x);
            av.y = ov.y * sigmoidf_(gv.y);
            av.z = ov.z * sigmoidf_(gv.z);
            av.w = ov.w * sigmoidf_(gv.w);
            *(float4*)&As[row*36 + c4*4] = av;
            int kr = idx >> 4, n4 = idx & 15;
            float4 bv = *(const float4*)&Wo[(size_t)(k0+kr)*CC + n0 + n4*4];
            *(float4*)&Bs[kr*68 + n4*4] = bv;
        }
        __syncthreads();
        #pragma unroll 8
        for(int kk=0; kk<32; kk++){
            u64 b0 = *(const u64*)&Bs[kk*68 + tn*8 + 0];
            u64 b1 = *(const u64*)&Bs[kk*68 + tn*8 + 2];
            u64 b2 = *(const u64*)&Bs[kk*68 + tn*8 + 4];
            u64 b3 = *(const u64*)&Bs[kk*68 + tn*8 + 6];
            #pragma unroll
            for(int r=0; r<4; r++){
                float a = As[(tm + 16*r)*36 + kk];
                u64 a2 = pk2(a, a);
                acc[r][0] = ffma2(a2, b0, acc[r][0]);
                acc[r][1] = ffma2(a2, b1, acc[r][1]);
                acc[r][2] = ffma2(a2, b2, acc[r][2]);
                acc[r][3] = ffma2(a2, b3, acc[r][3]);
            }
        }
    }
    #pragma unroll
    for(int r=0; r<4; r++){
        int m = m0 + tm + 16*r;
        #pragma unroll
        for(int p=0; p<4; p++){
            int n = n0 + tn*8 + 2*p;
            float2 vv = up2(acc[r][p]);
            vv.x += bo[n]; vv.y += bo[n+1];
            *(float2*)&out[(size_t)m*CC + n] = vv;
        }
    }
}

// ------------------------- launch -------------------------------------------
extern "C" void kernel_launch(void* const* d_in, const int* in_sizes, int n_in,
                              void* d_out, int out_size){
    const float* a     = (const float*)d_in[0];
    const float* z     = (const float*)d_in[1];
    const float* mask  = (const float*)d_in[2];
    const float* lnaw  = (const float*)d_in[3];
    const float* lnab  = (const float*)d_in[4];
    const float* lnzw  = (const float*)d_in[5];
    const float* lnzb  = (const float*)d_in[6];
    const float* Wz    = (const float*)d_in[7];
    const float* Wq    = (const float*)d_in[8];
    const float* Wk    = (const float*)d_in[9];
    const float* Wv    = (const float*)d_in[10];
    const float* Wg    = (const float*)d_in[11];
    const float* bg    = (const float*)d_in[12];
    const float* Wo    = (const float*)d_in[13];
    const float* bo    = (const float*)d_in[14];
    float* out = (float*)d_out;

    k_prep<<<1, 128>>>(lnzw, lnzb, Wz);
    k_lna<<<96, 256>>>(a, lnaw, lnab);
    k_proj<<<dim3(6, 12, 4), 128>>>(Wq, Wk, Wv, Wg, bg);
    k_bias<<<dim3(6, 768), 128>>>(z);
    k_attn<<<dim3(24, 16), 256>>>(mask);
    k_oproj<<<dim3(6, 12), 128>>>(Wo, bo, out);
}